// round 3
// baseline (speedup 1.0000x reference)
#include <cuda_runtime.h>
#include <cuda_fp16.h>
#include <stdint.h>

#define Bz 4
#define Nn 4096
#define Mm 4096
#define Cc 256

// ---------------- persistent device scratch (no runtime alloc) ----------------
__device__ __align__(16) float2 g_sl[Bz][Nn];   // source locs, invalid -> x=-1e18
__device__ __align__(16) float2 g_tl[Bz][Mm];   // target locs, invalid -> x=+1e18
__device__ float g_u[Bz][Mm];
__device__ float g_v[Bz][Nn];
__device__ unsigned char g_sok[Bz][Nn];
__device__ unsigned char g_has[Bz][Mm];
__device__ __align__(16) __half g_fT[Bz][Cc][Nn];   // feats transposed, fp16

// ---------------- mask dtype auto-detect (uint8 / int32 / float32) -----------
__device__ __forceinline__ int detect_fmt(const unsigned* w) {
    bool sawF = false, sawU = false;
    for (int i = 0; i < 64; i++) {
        unsigned v = w[i];
        if (v == 0x3F800000u) sawF = true;
        else if (v > 1u) {
            unsigned b0 = v & 255u, b1 = (v >> 8) & 255u, b2 = (v >> 16) & 255u, b3 = v >> 24;
            if (b0 <= 1u && b1 <= 1u && b2 <= 1u && b3 <= 1u) sawU = true;
            else sawF = true;
        }
    }
    if (sawF) return 2;
    if (sawU) return 0;
    return 1;
}
__device__ __forceinline__ bool read_mask(const void* p, int i, int fmt) {
    if (fmt == 0) return ((const unsigned char*)p)[i] != 0;
    if (fmt == 1) return ((const int*)p)[i] != 0;
    return ((const float*)p)[i] != 0.0f;
}

// ---------------- prep: decode masks, bake sentinels, init v=0 ---------------
__global__ void prep_kernel(const float* __restrict__ slocs,
                            const float* __restrict__ tlocs,
                            const void* __restrict__ smask,
                            const void* __restrict__ tmask) {
    __shared__ int sf[2];
    if (threadIdx.x == 0) {
        sf[0] = detect_fmt((const unsigned*)smask);
        sf[1] = detect_fmt((const unsigned*)tmask);
    }
    __syncthreads();
    int i = blockIdx.x * blockDim.x + threadIdx.x;
    if (i >= Bz * Nn) return;
    int b = i / Nn, n = i % Nn;

    bool sok = read_mask(smask, i, sf[0]);
    float sx = slocs[2 * i], sy = slocs[2 * i + 1];
    g_sl[b][n] = make_float2(sok ? sx : -1e18f, sy);
    g_sok[b][n] = sok ? 1 : 0;
    g_v[b][n] = 0.0f;

    bool tok = read_mask(tmask, i, sf[1]);
    float tx = tlocs[2 * i], ty = tlocs[2 * i + 1];
    g_tl[b][n] = make_float2(tok ? tx : 1e18f, ty);
}

// ---------------- feats f32 [b][n][c] -> fp16 transposed [b][c][n] -----------
__global__ void feats_transpose(const float* __restrict__ f) {
    __shared__ float tile[32][33];
    int b = blockIdx.z;
    int n0 = blockIdx.x * 32, c0 = blockIdx.y * 32;
    int tx = threadIdx.x, ty = threadIdx.y;   // 32 x 8
    #pragma unroll
    for (int j = 0; j < 4; j++) {
        int n = n0 + ty + j * 8;
        tile[ty + j * 8][tx] = f[((b * Nn + n) * Cc) + (c0 + tx)];
    }
    __syncthreads();
    #pragma unroll
    for (int j = 0; j < 4; j++) {
        int c = c0 + ty + j * 8;
        g_fT[b][c][n0 + tx] = __float2half(tile[tx][ty + j * 8]);
    }
}

// ---------------- streaming LSE: MODE 0 = u-step, MODE 1 = v-step ------------
// block = 256 threads = 8 warps; each warp owns 8 rows; grid = (4096/64, B)
template <int MODE>
__global__ __launch_bounds__(256) void lse_kernel() {
    const int b = blockIdx.y;
    const int warp = threadIdx.x >> 5, lane = threadIdx.x & 31;
    const int row0 = blockIdx.x * 64 + warp * 8;
    __shared__ __align__(16) float4 buf[1024];

    const float NEG_INV = -1.0f / 0.01000001f;

    float tx[8], ty[8], mx[8], ss[8];
    #pragma unroll
    for (int r = 0; r < 8; r++) {
        float2 p = (MODE == 0) ? g_tl[b][row0 + r] : g_sl[b][row0 + r];
        tx[r] = p.x; ty[r] = p.y;
        mx[r] = -1e30f; ss[r] = 0.0f;
    }
    int cnt0 = 0;

    for (int base = 0; base < 4096; base += 1024) {
        __syncthreads();
        for (int i = threadIdx.x; i < 1024; i += 256) {
            float2 p; float z;
            if (MODE == 0) { p = g_sl[b][base + i]; z = g_v[b][base + i]; }
            else           { p = g_tl[b][base + i]; z = g_u[b][base + i]; }
            buf[i] = make_float4(p.x, p.y, z, 0.0f);
        }
        __syncthreads();
        for (int i = lane; i < 1024; i += 32) {
            float4 q = buf[i];
            cnt0 += (q.z == 1.0e9f) ? 1 : 0;   // entries that are exactly 0 in log-domain
            #pragma unroll
            for (int r = 0; r < 8; r++) {
                float dx = __fadd_rn(tx[r], -q.x);
                float dy = __fadd_rn(ty[r], -q.y);
                float d2 = __fadd_rn(__fmul_rn(dx, dx), __fmul_rn(dy, dy));
                if (d2 < 0.04f) {
                    float x  = __fmaf_rn(d2, NEG_INV, q.z);
                    float dd = x - mx[r];
                    float e  = __expf(-fabsf(dd));
                    if (dd > 0.0f) { ss[r] = __fmaf_rn(ss[r], e, 1.0f); mx[r] = x; }
                    else           { ss[r] += e; }
                }
            }
        }
    }

    // butterfly reduce across lanes
    #pragma unroll
    for (int off = 16; off; off >>= 1) {
        cnt0 += __shfl_xor_sync(0xffffffffu, cnt0, off);
        #pragma unroll
        for (int r = 0; r < 8; r++) {
            float m2 = __shfl_xor_sync(0xffffffffu, mx[r], off);
            float s2 = __shfl_xor_sync(0xffffffffu, ss[r], off);
            float M  = fmaxf(mx[r], m2);
            ss[r] = ss[r] * __expf(mx[r] - M) + s2 * __expf(m2 - M);
            mx[r] = M;
        }
    }

    #pragma unroll
    for (int r = 0; r < 8; r++) {
        if (lane == r) {
            float m = mx[r], s = ss[r];
            bool anyvalid = (s > 0.0f);
            if (cnt0 > 0) {
                float M = fmaxf(m, 0.0f);
                s = s * __expf(m - M) + (float)cnt0 * __expf(0.0f - M);
                m = M;
            }
            float dual = (s == 0.0f) ? 1.0e9f : -(m + __logf(s));
            int row = row0 + r;
            if (MODE == 0) {
                g_u[b][row] = dual;
                g_has[b][row] = anyvalid ? 1 : 0;
            } else {
                g_v[b][row] = g_sok[b][row] ? dual : 0.0f;
            }
        }
    }
}

// ---------------- fused attn-recompute GEMM: out = exp(lk+u+v) @ feats -------
__device__ __forceinline__ void mma16816(float& c0, float& c1, float& c2, float& c3,
                                         unsigned a0, unsigned a1, unsigned a2, unsigned a3,
                                         unsigned b0, unsigned b1) {
    asm volatile(
        "mma.sync.aligned.m16n8k16.row.col.f32.f16.f16.f32 "
        "{%0,%1,%2,%3}, {%4,%5,%6,%7}, {%8,%9}, {%0,%1,%2,%3};\n"
        : "+f"(c0), "+f"(c1), "+f"(c2), "+f"(c3)
        : "r"(a0), "r"(a1), "r"(a2), "r"(a3), "r"(b0), "r"(b1));
}

__device__ __forceinline__ float attn_val(float txx, float tyy, float uu, float4 q) {
    const float NEG_INV = -1.0f / 0.01000001f;
    float dx = __fadd_rn(txx, -q.x);
    float dy = __fadd_rn(tyy, -q.y);
    float d2 = __fadd_rn(__fmul_rn(dx, dx), __fmul_rn(dy, dy));
    if (d2 < 0.04f)
        return __expf(__fadd_rn(__fmaf_rn(d2, NEG_INV, uu), q.z));
    return 0.0f;
}

__device__ __forceinline__ unsigned pack2(float x, float y) {
    __half2 h = __floats2half2_rn(x, y);
    return *reinterpret_cast<unsigned*>(&h);
}

#define GBM 128
#define GBC 128
#define GBK 64
#define SBSTRIDE 72   // half elements per smem B row (conflict-free: 144B = 36 words)

// 256 threads = 8 warps; each warp: 16 m-rows x full 128 c-cols (16 n-frags)
__global__ __launch_bounds__(256) void gemm_kernel(float* __restrict__ out) {
    const int b  = blockIdx.z;
    const int m0 = blockIdx.x * GBM;
    const int c0 = blockIdx.y * GBC;
    const int warp = threadIdx.x >> 5, lane = threadIdx.x & 31;
    const int gid = lane >> 2, tig = lane & 3;

    __shared__ __align__(16) __half sB[GBC][SBSTRIDE];  // [c][k]
    __shared__ __align__(16) float4 sS[GBK];            // (sx, sy, v, 0)

    const int rlo = m0 + warp * 16 + gid;
    const int rhi = rlo + 8;
    const float2 tlo = g_tl[b][rlo];
    const float2 thi = g_tl[b][rhi];
    const float  ulo = g_u[b][rlo];
    const float  uhi = g_u[b][rhi];
    const bool haslo = g_has[b][rlo] != 0;
    const bool hashi = g_has[b][rhi] != 0;

    float acc[16][4];
    #pragma unroll
    for (int j = 0; j < 16; j++) {
        acc[j][0] = 0.f; acc[j][1] = 0.f; acc[j][2] = 0.f; acc[j][3] = 0.f;
    }

    for (int n0 = 0; n0 < Nn; n0 += GBK) {
        __syncthreads();
        // stage feats chunk: 128 c-rows x 64 halves (128B) each
        {
            int idx = threadIdx.x;                 // 256 threads
            #pragma unroll
            for (int t = 0; t < 4; t++, idx += 256) {
                int row = idx >> 3, ch = idx & 7;  // 128 rows x 8 x 16B
                const uint4* src = reinterpret_cast<const uint4*>(&g_fT[b][c0 + row][n0]) + ch;
                *reinterpret_cast<uint4*>(&sB[row][ch * 8]) = *src;
            }
        }
        // stage source locs + v
        if (threadIdx.x < GBK) {
            int n = n0 + threadIdx.x;
            float2 p = g_sl[b][n];
            sS[threadIdx.x] = make_float4(p.x, p.y, g_v[b][n], 0.0f);
        }
        __syncthreads();

        #pragma unroll
        for (int kf = 0; kf < 4; kf++) {
            const int kb = kf * 16 + 2 * tig;
            float4 qa = sS[kb];
            float4 qb = sS[kb + 1];
            float4 qc = sS[kb + 8];
            float4 qd = sS[kb + 9];

            // A fragment computed directly in register layout
            float vla = attn_val(tlo.x, tlo.y, ulo, qa);
            float vlb = attn_val(tlo.x, tlo.y, ulo, qb);
            float vha = attn_val(thi.x, thi.y, uhi, qa);
            float vhb = attn_val(thi.x, thi.y, uhi, qb);
            float vlc = attn_val(tlo.x, tlo.y, ulo, qc);
            float vld = attn_val(tlo.x, tlo.y, ulo, qd);
            float vhc = attn_val(thi.x, thi.y, uhi, qc);
            float vhd = attn_val(thi.x, thi.y, uhi, qd);
            unsigned a0 = pack2(vla, vlb);
            unsigned a1 = pack2(vha, vhb);
            unsigned a2 = pack2(vlc, vld);
            unsigned a3 = pack2(vhc, vhd);

            #pragma unroll
            for (int j = 0; j < 16; j++) {
                const __half* brow = &sB[j * 8 + gid][kf * 16 + 2 * tig];
                unsigned b0 = *reinterpret_cast<const unsigned*>(brow);
                unsigned b1 = *reinterpret_cast<const unsigned*>(brow + 8);
                mma16816(acc[j][0], acc[j][1], acc[j][2], acc[j][3],
                         a0, a1, a2, a3, b0, b1);
            }
        }
    }

    // epilogue
    #pragma unroll
    for (int j = 0; j < 16; j++) {
        int c = c0 + j * 8 + 2 * tig;
        float2 vlo = haslo ? make_float2(acc[j][0], acc[j][1]) : make_float2(0.f, 0.f);
        float2 vhi = hashi ? make_float2(acc[j][2], acc[j][3]) : make_float2(0.f, 0.f);
        *reinterpret_cast<float2*>(&out[((b * Mm + rlo) * Cc) + c]) = vlo;
        *reinterpret_cast<float2*>(&out[((b * Mm + rhi) * Cc) + c]) = vhi;
    }
}

// ------------------------------- launch ---------------------------------------
extern "C" void kernel_launch(void* const* d_in, const int* in_sizes, int n_in,
                              void* d_out, int out_size) {
    const float* feats = (const float*)d_in[0];
    const float* slocs = (const float*)d_in[1];
    const float* tlocs = (const float*)d_in[2];
    const void*  smask = d_in[3];
    const void*  tmask = d_in[4];
    float* out = (float*)d_out;

    prep_kernel<<<(Bz * Nn + 255) / 256, 256>>>(slocs, tlocs, smask, tmask);
    feats_transpose<<<dim3(Nn / 32, Cc / 32, Bz), dim3(32, 8)>>>(feats);

    for (int it = 0; it < 3; it++) {
        lse_kernel<0><<<dim3(Mm / 64, Bz), 256>>>();
        lse_kernel<1><<<dim3(Nn / 64, Bz), 256>>>();
    }

    gemm_kernel<<<dim3(Mm / GBM, Cc / GBC, Bz), 256>>>(out);
}

// round 4
// speedup vs baseline: 1.5275x; 1.5275x over previous
#include <cuda_runtime.h>
#include <cuda_fp16.h>
#include <stdint.h>

#define Bz 4
#define Nn 4096
#define Mm 4096
#define Cc 256

// ---------------- persistent device scratch (no runtime alloc) ----------------
__device__ __align__(16) float2 g_sl0[Bz][Nn];  // original-order baked coords
__device__ __align__(16) float2 g_tl0[Bz][Mm];
__device__ unsigned char g_sok0[Bz][Nn];
__device__ int g_tkey[Bz][Mm];
__device__ int g_skey[Bz][Nn];
__device__ int g_tperm[Bz][Mm];                 // sorted pos -> orig idx
__device__ int g_sperm[Bz][Nn];

__device__ __align__(16) float2 g_sl[Bz][Nn];   // SORTED coords
__device__ __align__(16) float2 g_tl[Bz][Mm];
__device__ unsigned char g_sok[Bz][Nn];         // sorted
__device__ float g_u[Bz][Mm];                   // duals in sorted order
__device__ float g_v[Bz][Nn];
__device__ unsigned char g_has[Bz][Mm];         // sorted
__device__ __align__(16) float4 g_sbb[Bz][Nn / 32];  // chunk bboxes (minx,miny,maxx,maxy)
__device__ __align__(16) float4 g_tbb[Bz][Mm / 32];
__device__ int g_cnt0[3 * Bz];                  // #(u==1e9) per (iter, batch)
__device__ __align__(16) __half g_fT[Bz][Cc][Nn];    // feats fp16, transposed, SORTED n

// ---------------- mask dtype auto-detect (uint8 / int32 / float32) -----------
__device__ __forceinline__ int detect_fmt(const unsigned* w) {
    bool sawF = false, sawU = false;
    for (int i = 0; i < 64; i++) {
        unsigned v = w[i];
        if (v == 0x3F800000u) sawF = true;
        else if (v > 1u) {
            unsigned b0 = v & 255u, b1 = (v >> 8) & 255u, b2 = (v >> 16) & 255u, b3 = v >> 24;
            if (b0 <= 1u && b1 <= 1u && b2 <= 1u && b3 <= 1u) sawU = true;
            else sawF = true;
        }
    }
    if (sawF) return 2;
    if (sawU) return 0;
    return 1;
}
__device__ __forceinline__ bool read_mask(const void* p, int i, int fmt) {
    if (fmt == 0) return ((const unsigned char*)p)[i] != 0;
    if (fmt == 1) return ((const int*)p)[i] != 0;
    return ((const float*)p)[i] != 0.0f;
}

__device__ __forceinline__ unsigned spread4(unsigned x) {
    x &= 15u; x = (x | (x << 2)) & 0x33u; x = (x | (x << 1)) & 0x55u; return x;
}
__device__ __forceinline__ int morton_key(float x, float y) {
    int cx = (int)(x * 16.0f); cx = cx < 0 ? 0 : (cx > 15 ? 15 : cx);
    int cy = (int)(y * 16.0f); cy = cy < 0 ? 0 : (cy > 15 ? 15 : cy);
    return (int)(spread4((unsigned)cx) | (spread4((unsigned)cy) << 1));  // 0..255
}

// ---------------- prep: decode masks, bake sentinels, keys -------------------
__global__ void prep_kernel(const float* __restrict__ slocs,
                            const float* __restrict__ tlocs,
                            const void* __restrict__ smask,
                            const void* __restrict__ tmask) {
    __shared__ int sf[2];
    if (threadIdx.x == 0) {
        sf[0] = detect_fmt((const unsigned*)smask);
        sf[1] = detect_fmt((const unsigned*)tmask);
    }
    __syncthreads();
    int i = blockIdx.x * blockDim.x + threadIdx.x;
    if (blockIdx.x == 0 && threadIdx.x < 3 * Bz) g_cnt0[threadIdx.x] = 0;
    if (i >= Bz * Nn) return;
    int b = i / Nn, n = i % Nn;

    bool sok = read_mask(smask, i, sf[0]);
    float sx = slocs[2 * i], sy = slocs[2 * i + 1];
    g_sl0[b][n] = make_float2(sok ? sx : -1e18f, sy);
    g_sok0[b][n] = sok ? 1 : 0;
    g_skey[b][n] = sok ? morton_key(sx, sy) : 256;

    bool tok = read_mask(tmask, i, sf[1]);
    float tx = tlocs[2 * i], ty = tlocs[2 * i + 1];
    g_tl0[b][n] = make_float2(tok ? tx : 1e18f, ty);
    g_tkey[b][n] = tok ? morton_key(tx, ty) : 256;
}

// ---------------- bitonic sort of (key<<12 | idx): stable, deterministic -----
__global__ __launch_bounds__(1024) void sort_kernel() {
    __shared__ unsigned sk[4096];
    int side = blockIdx.x, b = blockIdx.y, tid = threadIdx.x;
    for (int i = tid; i < 4096; i += 1024) {
        int key = side ? g_skey[b][i] : g_tkey[b][i];
        sk[i] = ((unsigned)key << 12) | (unsigned)i;
    }
    __syncthreads();
    for (int k = 2; k <= 4096; k <<= 1) {
        for (int j = k >> 1; j >= 1; j >>= 1) {
            for (int i = tid; i < 4096; i += 1024) {
                int l = i ^ j;
                if (l > i) {
                    unsigned a = sk[i], c = sk[l];
                    bool up = ((i & k) == 0);
                    if ((a > c) == up) { sk[i] = c; sk[l] = a; }
                }
            }
            __syncthreads();
        }
    }
    for (int i = tid; i < 4096; i += 1024) {
        int idx = (int)(sk[i] & 0xFFFu);
        if (side) g_sperm[b][i] = idx; else g_tperm[b][i] = idx;
    }
}

// ---------------- scatter to sorted order + chunk bboxes ---------------------
__global__ void scatter_kernel() {
    int b = blockIdx.y, side = blockIdx.z;
    int i = blockIdx.x * 256 + threadIdx.x;
    int lane = threadIdx.x & 31;
    float2 p;
    if (side == 0) {
        int idx = g_tperm[b][i];
        p = g_tl0[b][idx];
        g_tl[b][i] = p;
    } else {
        int idx = g_sperm[b][i];
        p = g_sl0[b][idx];
        g_sl[b][i] = p;
        g_sok[b][i] = g_sok0[b][idx];
        g_v[b][i] = 0.0f;
    }
    // warp == one 32-chunk: bbox reduce
    float mnx = p.x, mxx = p.x, mny = p.y, mxy = p.y;
    #pragma unroll
    for (int off = 16; off; off >>= 1) {
        mnx = fminf(mnx, __shfl_xor_sync(0xffffffffu, mnx, off));
        mxx = fmaxf(mxx, __shfl_xor_sync(0xffffffffu, mxx, off));
        mny = fminf(mny, __shfl_xor_sync(0xffffffffu, mny, off));
        mxy = fmaxf(mxy, __shfl_xor_sync(0xffffffffu, mxy, off));
    }
    if (lane == 0) {
        int chunk = i >> 5;
        float4 bb = make_float4(mnx, mny, mxx, mxy);
        if (side == 0) g_tbb[b][chunk] = bb; else g_sbb[b][chunk] = bb;
    }
}

// ---------------- feats f32 [b][orig n][c] -> fp16 [b][c][sorted n] ----------
__global__ void feats_transpose(const float* __restrict__ f) {
    __shared__ float tile[32][33];
    int b = blockIdx.z;
    int n0 = blockIdx.x * 32, c0 = blockIdx.y * 32;
    int tx = threadIdx.x, ty = threadIdx.y;   // 32 x 8
    #pragma unroll
    for (int j = 0; j < 4; j++) {
        int n = n0 + ty + j * 8;
        int on = g_sperm[b][n];
        tile[ty + j * 8][tx] = f[((b * Nn + on) * Cc) + (c0 + tx)];
    }
    __syncthreads();
    #pragma unroll
    for (int j = 0; j < 4; j++) {
        int c = c0 + ty + j * 8;
        g_fT[b][c][n0 + tx] = __float2half(tile[tx][ty + j * 8]);
    }
}

// ---------------- streaming LSE with chunk skipping ---------------------------
// block = 256 threads = 8 warps; warp = 4 sorted rows x all 4096 opposing cols
template <int MODE>
__global__ __launch_bounds__(256) void lse_kernel(int iter) {
    const int b = blockIdx.y;
    const int warp = threadIdx.x >> 5, lane = threadIdx.x & 31;
    const int row0 = blockIdx.x * 32 + warp * 4;
    const float NEG_INV = -1.0f / 0.01000001f;

    float tx[4], ty[4], mx[4], ss[4];
    #pragma unroll
    for (int r = 0; r < 4; r++) {
        float2 p = (MODE == 0) ? g_tl[b][row0 + r] : g_sl[b][row0 + r];
        tx[r] = p.x; ty[r] = p.y;
        mx[r] = -1e30f; ss[r] = 0.0f;
    }
    float rmnx = fminf(fminf(tx[0], tx[1]), fminf(tx[2], tx[3]));
    float rmxx = fmaxf(fmaxf(tx[0], tx[1]), fmaxf(tx[2], tx[3]));
    float rmny = fminf(fminf(ty[0], ty[1]), fminf(ty[2], ty[3]));
    float rmxy = fmaxf(fmaxf(ty[0], ty[1]), fmaxf(ty[2], ty[3]));

    for (int c = 0; c < 128; c++) {
        float4 cb = (MODE == 0) ? g_sbb[b][c] : g_tbb[b][c];
        float ddx = fmaxf(fmaxf(cb.x - rmxx, rmnx - cb.z), 0.0f);
        float ddy = fmaxf(fmaxf(cb.y - rmxy, rmny - cb.w), 0.0f);
        if (ddx * ddx + ddy * ddy >= 0.0401f) continue;

        int n = c * 32 + lane;
        float2 p; float z;
        if (MODE == 0) { p = g_sl[b][n]; z = g_v[b][n]; }
        else           { p = g_tl[b][n]; z = g_u[b][n]; }
        #pragma unroll
        for (int r = 0; r < 4; r++) {
            float dx = __fadd_rn(tx[r], -p.x);
            float dy = __fadd_rn(ty[r], -p.y);
            float d2 = __fadd_rn(__fmul_rn(dx, dx), __fmul_rn(dy, dy));
            if (d2 < 0.04f) {
                float x  = __fmaf_rn(d2, NEG_INV, z);
                float dd = x - mx[r];
                float e  = __expf(-fabsf(dd));
                if (dd > 0.0f) { ss[r] = __fmaf_rn(ss[r], e, 1.0f); mx[r] = x; }
                else           { ss[r] += e; }
            }
        }
    }

    #pragma unroll
    for (int off = 16; off; off >>= 1) {
        #pragma unroll
        for (int r = 0; r < 4; r++) {
            float m2 = __shfl_xor_sync(0xffffffffu, mx[r], off);
            float s2 = __shfl_xor_sync(0xffffffffu, ss[r], off);
            float M  = fmaxf(mx[r], m2);
            ss[r] = ss[r] * __expf(mx[r] - M) + s2 * __expf(m2 - M);
            mx[r] = M;
        }
    }

    #pragma unroll
    for (int r = 0; r < 4; r++) {
        if (lane == r) {
            float m = mx[r], s = ss[r];
            int row = row0 + r;
            if (MODE == 0) {
                bool anyvalid = (s > 0.0f);
                float dual = anyvalid ? -(m + __logf(s)) : 1.0e9f;
                if (!anyvalid) atomicAdd(&g_cnt0[iter * Bz + b], 1);
                g_u[b][row] = dual;
                g_has[b][row] = anyvalid ? 1 : 0;
            } else {
                int cnt0 = g_cnt0[iter * Bz + b];
                if (cnt0 > 0) {
                    float M = fmaxf(m, 0.0f);
                    s = s * __expf(m - M) + (float)cnt0 * __expf(0.0f - M);
                    m = M;
                }
                float dual = (s == 0.0f) ? 1.0e9f : -(m + __logf(s));
                g_v[b][row] = g_sok[b][row] ? dual : 0.0f;
            }
        }
    }
}

// ---------------- fused attn-recompute GEMM with k-chunk skipping ------------
__device__ __forceinline__ void mma16816(float& c0, float& c1, float& c2, float& c3,
                                         unsigned a0, unsigned a1, unsigned a2, unsigned a3,
                                         unsigned b0, unsigned b1) {
    asm volatile(
        "mma.sync.aligned.m16n8k16.row.col.f32.f16.f16.f32 "
        "{%0,%1,%2,%3}, {%4,%5,%6,%7}, {%8,%9}, {%0,%1,%2,%3};\n"
        : "+f"(c0), "+f"(c1), "+f"(c2), "+f"(c3)
        : "r"(a0), "r"(a1), "r"(a2), "r"(a3), "r"(b0), "r"(b1));
}

__device__ __forceinline__ float attn_val(float txx, float tyy, float uu, float4 q) {
    const float NEG_INV = -1.0f / 0.01000001f;
    float dx = __fadd_rn(txx, -q.x);
    float dy = __fadd_rn(tyy, -q.y);
    float d2 = __fadd_rn(__fmul_rn(dx, dx), __fmul_rn(dy, dy));
    if (d2 < 0.04f)
        return __expf(__fadd_rn(__fmaf_rn(d2, NEG_INV, uu), q.z));
    return 0.0f;
}

__device__ __forceinline__ unsigned pack2(float x, float y) {
    __half2 h = __floats2half2_rn(x, y);
    return *reinterpret_cast<unsigned*>(&h);
}

#define GBM 128
#define GBC 128
#define GBK 64
#define SBSTRIDE 72

__global__ __launch_bounds__(256) void gemm_kernel(float* __restrict__ out) {
    const int b  = blockIdx.z;
    const int m0 = blockIdx.x * GBM;
    const int c0 = blockIdx.y * GBC;
    const int warp = threadIdx.x >> 5, lane = threadIdx.x & 31;
    const int gid = lane >> 2, tig = lane & 3;

    __shared__ __align__(16) __half sB[GBC][SBSTRIDE];
    __shared__ __align__(16) float4 sS[GBK];

    // block target bbox from 4 precomputed 32-chunk bboxes (uniform)
    float tmnx, tmxx, tmny, tmxy;
    {
        float4 b0 = g_tbb[b][(m0 >> 5) + 0], b1 = g_tbb[b][(m0 >> 5) + 1];
        float4 b2 = g_tbb[b][(m0 >> 5) + 2], b3 = g_tbb[b][(m0 >> 5) + 3];
        tmnx = fminf(fminf(b0.x, b1.x), fminf(b2.x, b3.x));
        tmny = fminf(fminf(b0.y, b1.y), fminf(b2.y, b3.y));
        tmxx = fmaxf(fmaxf(b0.z, b1.z), fmaxf(b2.z, b3.z));
        tmxy = fmaxf(fmaxf(b0.w, b1.w), fmaxf(b2.w, b3.w));
    }

    const int rlo = m0 + warp * 16 + gid;
    const int rhi = rlo + 8;
    const float2 tlo = g_tl[b][rlo];
    const float2 thi = g_tl[b][rhi];
    const float  ulo = g_u[b][rlo];
    const float  uhi = g_u[b][rhi];
    const bool haslo = g_has[b][rlo] != 0;
    const bool hashi = g_has[b][rhi] != 0;

    float acc[16][4];
    #pragma unroll
    for (int j = 0; j < 16; j++) {
        acc[j][0] = 0.f; acc[j][1] = 0.f; acc[j][2] = 0.f; acc[j][3] = 0.f;
    }

    for (int n0 = 0; n0 < Nn; n0 += GBK) {
        // uniform k-chunk skip test
        {
            float4 s0 = g_sbb[b][(n0 >> 5) + 0], s1 = g_sbb[b][(n0 >> 5) + 1];
            float smnx = fminf(s0.x, s1.x), smny = fminf(s0.y, s1.y);
            float smxx = fmaxf(s0.z, s1.z), smxy = fmaxf(s0.w, s1.w);
            float ddx = fmaxf(fmaxf(smnx - tmxx, tmnx - smxx), 0.0f);
            float ddy = fmaxf(fmaxf(smny - tmxy, tmny - smxy), 0.0f);
            if (ddx * ddx + ddy * ddy >= 0.0401f) continue;
        }
        __syncthreads();
        {
            int idx = threadIdx.x;
            #pragma unroll
            for (int t = 0; t < 4; t++, idx += 256) {
                int row = idx >> 3, ch = idx & 7;
                const uint4* src = reinterpret_cast<const uint4*>(&g_fT[b][c0 + row][n0]) + ch;
                *reinterpret_cast<uint4*>(&sB[row][ch * 8]) = *src;
            }
        }
        if (threadIdx.x < GBK) {
            int n = n0 + threadIdx.x;
            float2 p = g_sl[b][n];
            sS[threadIdx.x] = make_float4(p.x, p.y, g_v[b][n], 0.0f);
        }
        __syncthreads();

        #pragma unroll
        for (int kf = 0; kf < 4; kf++) {
            const int kb = kf * 16 + 2 * tig;
            float4 qa = sS[kb];
            float4 qb = sS[kb + 1];
            float4 qc = sS[kb + 8];
            float4 qd = sS[kb + 9];

            unsigned a0 = pack2(attn_val(tlo.x, tlo.y, ulo, qa), attn_val(tlo.x, tlo.y, ulo, qb));
            unsigned a1 = pack2(attn_val(thi.x, thi.y, uhi, qa), attn_val(thi.x, thi.y, uhi, qb));
            unsigned a2 = pack2(attn_val(tlo.x, tlo.y, ulo, qc), attn_val(tlo.x, tlo.y, ulo, qd));
            unsigned a3 = pack2(attn_val(thi.x, thi.y, uhi, qc), attn_val(thi.x, thi.y, uhi, qd));

            #pragma unroll
            for (int j = 0; j < 16; j++) {
                const __half* brow = &sB[j * 8 + gid][kf * 16 + 2 * tig];
                unsigned b0 = *reinterpret_cast<const unsigned*>(brow);
                unsigned b1 = *reinterpret_cast<const unsigned*>(brow + 8);
                mma16816(acc[j][0], acc[j][1], acc[j][2], acc[j][3],
                         a0, a1, a2, a3, b0, b1);
            }
        }
    }

    // epilogue: scatter to original row order
    const int orlo = g_tperm[b][rlo];
    const int orhi = g_tperm[b][rhi];
    #pragma unroll
    for (int j = 0; j < 16; j++) {
        int c = c0 + j * 8 + 2 * tig;
        float2 vlo = haslo ? make_float2(acc[j][0], acc[j][1]) : make_float2(0.f, 0.f);
        float2 vhi = hashi ? make_float2(acc[j][2], acc[j][3]) : make_float2(0.f, 0.f);
        *reinterpret_cast<float2*>(&out[((b * Mm + orlo) * Cc) + c]) = vlo;
        *reinterpret_cast<float2*>(&out[((b * Mm + orhi) * Cc) + c]) = vhi;
    }
}

// ------------------------------- launch ---------------------------------------
extern "C" void kernel_launch(void* const* d_in, const int* in_sizes, int n_in,
                              void* d_out, int out_size) {
    const float* feats = (const float*)d_in[0];
    const float* slocs = (const float*)d_in[1];
    const float* tlocs = (const float*)d_in[2];
    const void*  smask = d_in[3];
    const void*  tmask = d_in[4];
    float* out = (float*)d_out;

    prep_kernel<<<(Bz * Nn + 255) / 256, 256>>>(slocs, tlocs, smask, tmask);
    sort_kernel<<<dim3(2, Bz), 1024>>>();
    scatter_kernel<<<dim3(Nn / 256, Bz, 2), 256>>>();
    feats_transpose<<<dim3(Nn / 32, Cc / 32, Bz), dim3(32, 8)>>>(feats);

    for (int it = 0; it < 3; it++) {
        lse_kernel<0><<<dim3(Mm / 32, Bz), 256>>>(it);
        lse_kernel<1><<<dim3(Nn / 32, Bz), 256>>>(it);
    }

    gemm_kernel<<<dim3(Mm / GBM, Cc / GBC, Bz), 256>>>(out);
}